// round 1
// baseline (speedup 1.0000x reference)
#include <cuda_runtime.h>
#include <math.h>

// Problem dims
#define NTOK   2048
#define DMOD   1024
#define NHEAD  16
#define DHEAD  64
#define DFFN   4096
#define NLAYER 6

// ---------------- scratch (no allocations allowed) ----------------
__device__ float g_h   [NTOK*DMOD];
__device__ float g_h2  [NTOK*DMOD];
__device__ float g_Q   [NHEAD*NTOK*DHEAD];
__device__ float g_K   [NHEAD*NTOK*DHEAD];
__device__ float g_V   [NHEAD*NTOK*DHEAD];
__device__ float g_attn[NHEAD*NTOK*DHEAD];
__device__ float g_Z   [NTOK*DMOD];
__device__ float g_O   [NTOK*DMOD];
__device__ float g_F   [NTOK*DFFN];
__device__ float g_R   [NTOK*DMOD];
__device__ float g_M   [NHEAD*DHEAD*DHEAD];
__device__ float g_LSE [NHEAD*NTOK];
__device__ float g_c   [NHEAD*DHEAD];

// ---------------- embedding + positional encoding ----------------
// Mimic the reference fp32 op sequence: factor = exp((2j/1024) * -log(1e4)),
// term = (n+1)*factor, P[2j]=sin(term), P[2j+1]=cos(term).
__global__ void __launch_bounds__(256) embed_pe_kernel(
    const int* __restrict__ X, const float* __restrict__ emb, float* __restrict__ h)
{
    int n = blockIdx.x;
    int tid = threadIdx.x;
    int d0 = tid * 4;                       // 4 elems = 2 (sin,cos) pairs
    long ebase = (long)X[n] * DMOD;
    float4 e = *(const float4*)&emb[ebase + d0];

    int j0 = d0 >> 1;                       // pair index
    const float negln = -9.2103403719761836f;   // -log(10000)
    float c0 = ((float)(2*j0)     / 1024.0f) * negln;
    float c1 = ((float)(2*(j0+1)) / 1024.0f) * negln;
    float p = (float)(n + 1);
    float t0 = p * expf(c0);
    float t1 = p * expf(c1);

    float4 o;
    o.x = e.x + sinf(t0);
    o.y = e.y + cosf(t0);
    o.z = e.z + sinf(t1);
    o.w = e.w + cosf(t1);
    *(float4*)&h[(long)n*DMOD + d0] = o;
}

// ---------------- generic tiled fp32 GEMM ----------------
// C[z] = alpha * (A[z] @ B[z]) + bbeta * bias[z]  (+ optional ReLU)
// All matrices row-major. Grid must exactly tile M,N. K % BK == 0.
template<int BM, int BN, int BK, int TM, int TN, bool RELU>
__global__ void __launch_bounds__(256) gemm_k(
    const float* __restrict__ A, const float* __restrict__ B,
    const float* __restrict__ bias, float* __restrict__ C,
    int K, int lda, int ldb, int ldc,
    long sA, long sB, long sBias, long sC,
    float alpha, float bbeta)
{
    constexpr int THREADS = (BM/TM) * (BN/TN);
    A    += (long)blockIdx.z * sA;
    B    += (long)blockIdx.z * sB;
    bias += (long)blockIdx.z * sBias;
    C    += (long)blockIdx.z * sC;

    const int m0 = blockIdx.y * BM;
    const int n0 = blockIdx.x * BN;

    __shared__ __align__(16) float As[BK][BM];
    __shared__ __align__(16) float Bs[BK][BN];

    const int tid = threadIdx.x;
    const int tx  = tid % (BN/TN);
    const int ty  = tid / (BN/TN);

    float acc[TM][TN];
    #pragma unroll
    for (int i = 0; i < TM; i++)
        #pragma unroll
        for (int j = 0; j < TN; j++) acc[i][j] = 0.0f;

    constexpr int A_F4 = BM*BK/4;
    constexpr int B_F4 = BN*BK/4;

    for (int k0 = 0; k0 < K; k0 += BK) {
        #pragma unroll
        for (int i = tid; i < A_F4; i += THREADS) {
            int row = i / (BK/4);
            int kk  = (i % (BK/4)) * 4;
            float4 v = *(const float4*)&A[(long)(m0+row)*lda + k0 + kk];
            As[kk+0][row] = v.x; As[kk+1][row] = v.y;
            As[kk+2][row] = v.z; As[kk+3][row] = v.w;
        }
        #pragma unroll
        for (int i = tid; i < B_F4; i += THREADS) {
            int kk  = i / (BN/4);
            int col = (i % (BN/4)) * 4;
            *(float4*)&Bs[kk][col] = *(const float4*)&B[(long)(k0+kk)*ldb + n0 + col];
        }
        __syncthreads();

        #pragma unroll
        for (int kk = 0; kk < BK; kk++) {
            float a[TM], b[TN];
            #pragma unroll
            for (int i = 0; i < TM; i += 4) {
                float4 t = *(const float4*)&As[kk][ty*TM + i];
                a[i]=t.x; a[i+1]=t.y; a[i+2]=t.z; a[i+3]=t.w;
            }
            #pragma unroll
            for (int j = 0; j < TN; j += 4) {
                float4 t = *(const float4*)&Bs[kk][tx*TN + j];
                b[j]=t.x; b[j+1]=t.y; b[j+2]=t.z; b[j+3]=t.w;
            }
            #pragma unroll
            for (int i = 0; i < TM; i++)
                #pragma unroll
                for (int j = 0; j < TN; j++)
                    acc[i][j] += a[i] * b[j];
        }
        __syncthreads();
    }

    #pragma unroll
    for (int i = 0; i < TM; i++) {
        int row = m0 + ty*TM + i;
        #pragma unroll
        for (int j = 0; j < TN; j += 4) {
            int col = n0 + tx*TN + j;
            float4 o;
            o.x = alpha*acc[i][j+0] + bbeta*bias[col+0];
            o.y = alpha*acc[i][j+1] + bbeta*bias[col+1];
            o.z = alpha*acc[i][j+2] + bbeta*bias[col+2];
            o.w = alpha*acc[i][j+3] + bbeta*bias[col+3];
            if (RELU) {
                o.x = fmaxf(o.x, 0.f); o.y = fmaxf(o.y, 0.f);
                o.z = fmaxf(o.z, 0.f); o.w = fmaxf(o.w, 0.f);
            }
            *(float4*)&C[(long)row*ldc + col] = o;
        }
    }
}

// ---------------- M[h] = K[h]^T @ V[h]  (64x64, reduce over 2048) ----------------
// grid (8 n-splits, NHEAD). Partial results atomically accumulated into g_M.
__global__ void __launch_bounds__(256) ktv_kernel(
    const float* __restrict__ Kmat, const float* __restrict__ V, float* __restrict__ M)
{
    int h = blockIdx.y, split = blockIdx.x;
    const float* Kh = Kmat + (long)h*NTOK*DHEAD;
    const float* Vh = V    + (long)h*NTOK*DHEAD;
    __shared__ __align__(16) float Ks[32][68];
    __shared__ __align__(16) float Vs[32][68];
    int tid = threadIdx.x, tx = tid & 15, ty = tid >> 4;
    float acc[4][4] = {};
    int nbeg = split * 256;
    for (int n0 = nbeg; n0 < nbeg + 256; n0 += 32) {
        for (int i = tid; i < 512; i += 256) {
            int r = i >> 4, c4 = (i & 15) << 2;
            *(float4*)&Ks[r][c4] = *(const float4*)&Kh[(long)(n0+r)*DHEAD + c4];
            *(float4*)&Vs[r][c4] = *(const float4*)&Vh[(long)(n0+r)*DHEAD + c4];
        }
        __syncthreads();
        #pragma unroll
        for (int n = 0; n < 32; n++) {
            float4 a = *(const float4*)&Ks[n][ty*4];
            float4 b = *(const float4*)&Vs[n][tx*4];
            float av[4] = {a.x, a.y, a.z, a.w};
            float bv[4] = {b.x, b.y, b.z, b.w};
            #pragma unroll
            for (int ik = 0; ik < 4; ik++)
                #pragma unroll
                for (int iv = 0; iv < 4; iv++)
                    acc[ik][iv] += av[ik] * bv[iv];
        }
        __syncthreads();
    }
    float* Mh = M + h*DHEAD*DHEAD;
    #pragma unroll
    for (int ik = 0; ik < 4; ik++)
        #pragma unroll
        for (int iv = 0; iv < 4; iv++)
            atomicAdd(&Mh[(ty*4+ik)*DHEAD + tx*4+iv], acc[ik][iv]);
}

// ---------------- LSE[h,m] = logsumexp_n ( Q[h,n]·K[h,m] / 8 ) ----------------
// grid (NTOK/64 m-tiles, NHEAD). Fused GEMM + online logsumexp, S never stored.
__global__ void __launch_bounds__(256) lse_kernel(
    const float* __restrict__ Q, const float* __restrict__ Kmat, float* __restrict__ LSE)
{
    int h  = blockIdx.y;
    int m0 = blockIdx.x * 64;
    const float* Qh = Q    + (long)h*NTOK*DHEAD;
    const float* Kh = Kmat + (long)h*NTOK*DHEAD;

    __shared__ __align__(16) float Ks[64][68];   // [k][m] transposed
    __shared__ __align__(16) float Qs[64][68];   // [k][n] transposed
    __shared__ float runmax[64], runsum[64];

    int tid = threadIdx.x, tx = tid & 15, ty = tid >> 4;

    for (int i = tid; i < 64*16; i += 256) {
        int m = i >> 4, k4 = (i & 15) << 2;
        float4 v = *(const float4*)&Kh[(long)(m0+m)*DHEAD + k4];
        Ks[k4+0][m]=v.x; Ks[k4+1][m]=v.y; Ks[k4+2][m]=v.z; Ks[k4+3][m]=v.w;
    }
    if (tid < 64) { runmax[tid] = -1e30f; runsum[tid] = 0.0f; }
    __syncthreads();

    for (int n0 = 0; n0 < NTOK; n0 += 64) {
        for (int i = tid; i < 64*16; i += 256) {
            int n = i >> 4, k4 = (i & 15) << 2;
            float4 v = *(const float4*)&Qh[(long)(n0+n)*DHEAD + k4];
            Qs[k4+0][n]=v.x; Qs[k4+1][n]=v.y; Qs[k4+2][n]=v.z; Qs[k4+3][n]=v.w;
        }
        __syncthreads();

        float s[4][4];
        #pragma unroll
        for (int i = 0; i < 4; i++)
            #pragma unroll
            for (int j = 0; j < 4; j++) s[i][j] = 0.0f;

        #pragma unroll
        for (int k = 0; k < 64; k++) {
            float4 a = *(const float4*)&Ks[k][ty*4];
            float4 b = *(const float4*)&Qs[k][tx*4];
            float av[4] = {a.x, a.y, a.z, a.w};
            float bv[4] = {b.x, b.y, b.z, b.w};
            #pragma unroll
            for (int im = 0; im < 4; im++)
                #pragma unroll
                for (int in = 0; in < 4; in++)
                    s[im][in] += av[im] * bv[in];
        }

        #pragma unroll
        for (int im = 0; im < 4; im++) {
            float v0 = s[im][0]*0.125f, v1 = s[im][1]*0.125f;
            float v2 = s[im][2]*0.125f, v3 = s[im][3]*0.125f;
            float mx = fmaxf(fmaxf(v0, v1), fmaxf(v2, v3));
            #pragma unroll
            for (int d = 1; d < 16; d <<= 1)
                mx = fmaxf(mx, __shfl_xor_sync(0xffffffffu, mx, d));
            float se = expf(v0-mx) + expf(v1-mx) + expf(v2-mx) + expf(v3-mx);
            #pragma unroll
            for (int d = 1; d < 16; d <<= 1)
                se += __shfl_xor_sync(0xffffffffu, se, d);
            if (tx == 0) {                 // one owner lane per m row
                int m = ty*4 + im;
                float om = runmax[m], os = runsum[m];
                float nm = fmaxf(om, mx);
                runsum[m] = os*expf(om-nm) + se*expf(mx-nm);
                runmax[m] = nm;
            }
        }
        __syncthreads();
    }
    if (tid < 64)
        LSE[h*NTOK + m0 + tid] = runmax[tid] + logf(runsum[tid]);
}

// ---------------- c[h,v] = sum_m LSE[h,m] * V[h,m,v] ----------------
__global__ void __launch_bounds__(256) cvec_kernel(
    const float* __restrict__ V, const float* __restrict__ LSE, float* __restrict__ c)
{
    int h = blockIdx.x, tid = threadIdx.x;
    int v = tid & 63, part = tid >> 6;
    const float* Vh = V   + (long)h*NTOK*DHEAD;
    const float* Lh = LSE + (long)h*NTOK;
    float s = 0.0f;
    for (int m = part*512; m < part*512 + 512; m++)
        s += Lh[m] * Vh[(long)m*DHEAD + v];
    __shared__ float sh[256];
    sh[tid] = s;
    __syncthreads();
    if (part == 0)
        c[h*DHEAD + v] = sh[v] + sh[64+v] + sh[128+v] + sh[192+v];
}

// ---------------- Z[n, h*64+v] = attn[h,n,v] ----------------
__global__ void __launch_bounds__(256) transpose_attn_kernel(
    const float* __restrict__ attn, float* __restrict__ Z)
{
    int i = blockIdx.x * 256 + threadIdx.x;     // float4 index
    int h   = i >> 15;                          // NTOK*DHEAD/4 = 32768 per head
    int rem = i & 32767;
    int n   = rem >> 4;
    int v4  = (rem & 15) << 2;
    float4 val = *(const float4*)&attn[(long)i << 2];
    *(float4*)&Z[(long)n*DMOD + h*DHEAD + v4] = val;
}

// ---------------- layer norm: out = g/std * (x+r - mean) + b  (ddof=1) ----------------
__device__ __forceinline__ float blockReduceSum256(float v)
{
    __shared__ float sh[8];
    int lane = threadIdx.x & 31, w = threadIdx.x >> 5;
    #pragma unroll
    for (int d = 16; d; d >>= 1) v += __shfl_xor_sync(0xffffffffu, v, d);
    __syncthreads();
    if (lane == 0) sh[w] = v;
    __syncthreads();
    float t = 0.0f;
    #pragma unroll
    for (int i = 0; i < 8; i++) t += sh[i];
    return t;
}

__global__ void __launch_bounds__(256) ln_kernel(
    const float* __restrict__ x, const float* __restrict__ r,
    const float* __restrict__ g, const float* __restrict__ b,
    float* __restrict__ out)
{
    int row = blockIdx.x, tid = threadIdx.x;
    long base = (long)row * DMOD;
    float4 xv = *(const float4*)&x[base + tid*4];
    float4 rv = *(const float4*)&r[base + tid*4];
    float v[4] = {xv.x+rv.x, xv.y+rv.y, xv.z+rv.z, xv.w+rv.w};

    float s = v[0]+v[1]+v[2]+v[3];
    s = blockReduceSum256(s);
    float mean = s * (1.0f/1024.0f);

    float d0=v[0]-mean, d1=v[1]-mean, d2=v[2]-mean, d3=v[3]-mean;
    float ss = d0*d0 + d1*d1 + d2*d2 + d3*d3;
    ss = blockReduceSum256(ss);
    float invstd = rsqrtf(ss * (1.0f/1023.0f));

    float4 gv = *(const float4*)&g[base + tid*4];
    float4 bv = *(const float4*)&b[base + tid*4];
    float4 o;
    o.x = gv.x*invstd*d0 + bv.x;
    o.y = gv.y*invstd*d1 + bv.y;
    o.z = gv.z*invstd*d2 + bv.z;
    o.w = gv.w*invstd*d3 + bv.w;
    *(float4*)&out[base + tid*4] = o;
}

// ---------------- driver ----------------
extern "C" void kernel_launch(void* const* d_in, const int* in_sizes, int n_in,
                              void* d_out, int out_size)
{
    const int*   X   = (const int*)  d_in[0];
    const float* emb = (const float*)d_in[1];
    const float* WQ  = (const float*)d_in[2];
    const float* bQ  = (const float*)d_in[3];
    const float* WK  = (const float*)d_in[4];
    const float* bK  = (const float*)d_in[5];
    const float* WV  = (const float*)d_in[6];
    const float* bV  = (const float*)d_in[7];
    const float* WO  = (const float*)d_in[8];
    const float* bO  = (const float*)d_in[9];
    const float* W1  = (const float*)d_in[10];
    const float* b1  = (const float*)d_in[11];
    const float* W2  = (const float*)d_in[12];
    const float* b2  = (const float*)d_in[13];
    const float* g1  = (const float*)d_in[14];
    const float* be1 = (const float*)d_in[15];
    const float* g2  = (const float*)d_in[16];
    const float* be2 = (const float*)d_in[17];
    float* out = (float*)d_out;

    float *h_, *h2, *Qb, *Kb, *Vb, *attnb, *Zb, *Ob, *Fb, *Rb, *Mb, *LSEb, *cb;
    cudaGetSymbolAddress((void**)&h_,   g_h);
    cudaGetSymbolAddress((void**)&h2,   g_h2);
    cudaGetSymbolAddress((void**)&Qb,   g_Q);
    cudaGetSymbolAddress((void**)&Kb,   g_K);
    cudaGetSymbolAddress((void**)&Vb,   g_V);
    cudaGetSymbolAddress((void**)&attnb,g_attn);
    cudaGetSymbolAddress((void**)&Zb,   g_Z);
    cudaGetSymbolAddress((void**)&Ob,   g_O);
    cudaGetSymbolAddress((void**)&Fb,   g_F);
    cudaGetSymbolAddress((void**)&Rb,   g_R);
    cudaGetSymbolAddress((void**)&Mb,   g_M);
    cudaGetSymbolAddress((void**)&LSEb, g_LSE);
    cudaGetSymbolAddress((void**)&cb,   g_c);

    embed_pe_kernel<<<NTOK, 256>>>(X, emb, h_);

    for (int l = 0; l < NLAYER; l++) {
        const float* wq = WQ + (long)l*NHEAD*DMOD*DHEAD;
        const float* wk = WK + (long)l*NHEAD*DMOD*DHEAD;
        const float* wv = WV + (long)l*NHEAD*DMOD*DHEAD;
        const float* bq = bQ + (long)l*NHEAD*DHEAD;
        const float* bk = bK + (long)l*NHEAD*DHEAD;
        const float* bv = bV + (long)l*NHEAD*DHEAD;

        // Q/K/V per-head projections: [2048,1024]@[1024,64]+b, z over heads
        dim3 gqkv(1, NTOK/128, NHEAD);
        gemm_k<128,64,8,8,4,false><<<gqkv, 256>>>(h_, wq, bq, Qb,
            DMOD, DMOD, DHEAD, DHEAD, 0, (long)DMOD*DHEAD, DHEAD, (long)NTOK*DHEAD, 1.f, 1.f);
        gemm_k<128,64,8,8,4,false><<<gqkv, 256>>>(h_, wk, bk, Kb,
            DMOD, DMOD, DHEAD, DHEAD, 0, (long)DMOD*DHEAD, DHEAD, (long)NTOK*DHEAD, 1.f, 1.f);
        gemm_k<128,64,8,8,4,false><<<gqkv, 256>>>(h_, wv, bv, Vb,
            DMOD, DMOD, DHEAD, DHEAD, 0, (long)DMOD*DHEAD, DHEAD, (long)NTOK*DHEAD, 1.f, 1.f);

        // M = K^T V per head
        cudaMemsetAsync(Mb, 0, sizeof(float)*NHEAD*DHEAD*DHEAD, 0);
        ktv_kernel<<<dim3(8, NHEAD), 256>>>(Kb, Vb, Mb);

        // column-wise logsumexp of S (over queries), fused
        lse_kernel<<<dim3(NTOK/64, NHEAD), 256>>>(Qb, Kb, LSEb);

        // c[h] = LSE[h] · V[h]
        cvec_kernel<<<NHEAD, 256>>>(Vb, LSEb, cb);

        // attn[h] = 0.125 * Q[h] @ M[h] - c[h]
        gemm_k<128,64,8,8,4,false><<<gqkv, 256>>>(Qb, Mb, cb, attnb,
            DHEAD, DHEAD, DHEAD, DHEAD,
            (long)NTOK*DHEAD, (long)DHEAD*DHEAD, DHEAD, (long)NTOK*DHEAD, 0.125f, -1.f);

        // concat heads
        transpose_attn_kernel<<<(NHEAD*NTOK*DHEAD/4)/256, 256>>>(attnb, Zb);

        // output projection
        gemm_k<128,128,8,8,8,false><<<dim3(DMOD/128, NTOK/128, 1), 256>>>(
            Zb, WO + (long)l*DMOD*DMOD, bO + (long)l*DMOD, Ob,
            DMOD, DMOD, DMOD, DMOD, 0,0,0,0, 1.f, 1.f);

        // h2 = LN(h + O)
        ln_kernel<<<NTOK, 256>>>(h_, Ob, g1 + (long)l*NTOK*DMOD, be1 + (long)l*NTOK*DMOD, h2);

        // FFN
        gemm_k<128,128,8,8,8,true><<<dim3(DFFN/128, NTOK/128, 1), 256>>>(
            h2, W1 + (long)l*DMOD*DFFN, b1 + (long)l*DFFN, Fb,
            DMOD, DMOD, DFFN, DFFN, 0,0,0,0, 1.f, 1.f);
        gemm_k<128,128,8,8,8,false><<<dim3(DMOD/128, NTOK/128, 1), 256>>>(
            Fb, W2 + (long)l*DFFN*DMOD, b2 + (long)l*DMOD, Rb,
            DFFN, DFFN, DMOD, DMOD, 0,0,0,0, 1.f, 1.f);

        // h = LN(h2 + R)  (last layer writes d_out directly)
        float* dst = (l == NLAYER-1) ? out : h_;
        ln_kernel<<<NTOK, 256>>>(h2, Rb, g2 + (long)l*NTOK*DMOD, be2 + (long)l*NTOK*DMOD, dst);
    }
}

// round 2
// speedup vs baseline: 3.2196x; 3.2196x over previous
#include <cuda_runtime.h>
#include <math.h>
#include <stdint.h>

// Problem dims
#define NTOK   2048
#define DMOD   1024
#define NHEAD  16
#define DHEAD  64
#define DFFN   4096
#define NLAYER 6

// ---------------- scratch (no allocations allowed) ----------------
__device__ float g_h   [NTOK*DMOD];
__device__ float g_h2  [NTOK*DMOD];
__device__ float g_Q   [NHEAD*NTOK*DHEAD];
__device__ float g_K   [NHEAD*NTOK*DHEAD];
__device__ float g_V   [NHEAD*NTOK*DHEAD];
__device__ float g_Z   [NTOK*DMOD];
__device__ float g_O   [NTOK*DMOD];
__device__ float g_F   [NTOK*DFFN];
__device__ float g_R   [NTOK*DMOD];
__device__ float g_M   [NHEAD*DHEAD*DHEAD];
__device__ float g_LSE [NHEAD*NTOK];
__device__ float g_c   [NHEAD*DHEAD];

// ---------------- tf32 helpers ----------------
__device__ __forceinline__ uint32_t f2tf32(float x) {
    uint32_t r;
    asm("cvt.rna.tf32.f32 %0, %1;" : "=r"(r) : "f"(x));
    return r;
}
__device__ __forceinline__ float4 cvt4(float4 v) {
    float4 o;
    o.x = __uint_as_float(f2tf32(v.x));
    o.y = __uint_as_float(f2tf32(v.y));
    o.z = __uint_as_float(f2tf32(v.z));
    o.w = __uint_as_float(f2tf32(v.w));
    return o;
}
__device__ __forceinline__ void mma8(float c[4], const uint32_t a[4], const uint32_t b[2]) {
    asm volatile(
        "mma.sync.aligned.m16n8k8.row.col.f32.tf32.tf32.f32 "
        "{%0,%1,%2,%3},{%4,%5,%6,%7},{%8,%9},{%0,%1,%2,%3};"
        : "+f"(c[0]), "+f"(c[1]), "+f"(c[2]), "+f"(c[3])
        : "r"(a[0]), "r"(a[1]), "r"(a[2]), "r"(a[3]), "r"(b[0]), "r"(b[1]));
}

// ---------------- embedding + positional encoding ----------------
__global__ void __launch_bounds__(256) embed_pe_kernel(
    const int* __restrict__ X, const float* __restrict__ emb, float* __restrict__ h)
{
    int n = blockIdx.x;
    int tid = threadIdx.x;
    int d0 = tid * 4;
    long ebase = (long)X[n] * DMOD;
    float4 e = *(const float4*)&emb[ebase + d0];

    int j0 = d0 >> 1;
    const float negln = -9.2103403719761836f;   // -log(10000)
    float c0 = ((float)(2*j0)     / 1024.0f) * negln;
    float c1 = ((float)(2*(j0+1)) / 1024.0f) * negln;
    float p = (float)(n + 1);
    float t0 = p * expf(c0);
    float t1 = p * expf(c1);

    float4 o;
    o.x = e.x + sinf(t0);
    o.y = e.y + cosf(t0);
    o.z = e.z + sinf(t1);
    o.w = e.w + cosf(t1);
    *(float4*)&h[(long)n*DMOD + d0] = o;
}

// ---------------- tf32 tensor-core GEMM ----------------
// C[z] = alpha * (A[z] @ B[z]) + bbeta * bias[z]  (+ optional ReLU)
// Row-major. 256 threads, 8 warps as 2(M)x4(N). BK=32 (4 tf32 k-steps).
// Swizzled shared layout: A[m][k^((m&7)<<2)], B[k][n^((k&3)<<3)] -> conflict-free
// fragment reads AND 16B-aligned float4 stores.
template<int BM, int BN, bool RELU>
__global__ void __launch_bounds__(256, 1) mma_gemm(
    const float* __restrict__ A, const float* __restrict__ B,
    const float* __restrict__ bias, float* __restrict__ C,
    int K, int lda, int ldb, int ldc,
    long sA, long sB, long sBias, long sC,
    float alpha, float bbeta)
{
    constexpr int BK = 32;
    constexpr int WM = BM / 2, WN = BN / 4;
    constexpr int MT = WM / 16, NT = WN / 8;
    constexpr int AV = (BM * BK / 4) / 256;   // float4 per thread (A tile)
    constexpr int BV = (BK * BN / 4) / 256;   // float4 per thread (B tile)

    extern __shared__ float sm[];
    float* As = sm;                 // [2][BM*BK]
    float* Bs = sm + 2 * BM * BK;   // [2][BK*BN]

    A    += (long)blockIdx.z * sA;
    B    += (long)blockIdx.z * sB;
    bias += (long)blockIdx.z * sBias;
    C    += (long)blockIdx.z * sC;

    const int m0 = blockIdx.y * BM;
    const int n0 = blockIdx.x * BN;
    const int tid = threadIdx.x, wid = tid >> 5, lane = tid & 31;
    const int wm = wid >> 2, wn = wid & 3;
    const int grp = lane >> 2, tig = lane & 3;

    float acc[MT][NT][4] = {};
    float4 ar[AV], br[BV];

    auto ldgAB = [&](int k0) {
        #pragma unroll
        for (int t = 0; t < AV; t++) {
            int i = tid + t * 256;
            int r = i >> 3, c = (i & 7) * 4;
            ar[t] = *(const float4*)&A[(long)(m0 + r) * lda + k0 + c];
        }
        #pragma unroll
        for (int t = 0; t < BV; t++) {
            int i = tid + t * 256;
            int r = i / (BN / 4), c = (i % (BN / 4)) * 4;
            br[t] = *(const float4*)&B[(long)(k0 + r) * ldb + n0 + c];
        }
    };
    auto sts = [&](int buf) {
        float* Ab = As + buf * BM * BK;
        float* Bb = Bs + buf * BK * BN;
        #pragma unroll
        for (int t = 0; t < AV; t++) {
            int i = tid + t * 256;
            int r = i >> 3, c = (i & 7) * 4;
            *(float4*)&Ab[r * BK + (c ^ ((r & 7) << 2))] = cvt4(ar[t]);
        }
        #pragma unroll
        for (int t = 0; t < BV; t++) {
            int i = tid + t * 256;
            int r = i / (BN / 4), c = (i % (BN / 4)) * 4;
            *(float4*)&Bb[r * BN + (c ^ ((r & 3) << 3))] = cvt4(br[t]);
        }
    };
    auto compute = [&](int buf) {
        const float* Ab = As + buf * BM * BK;
        const float* Bb = Bs + buf * BK * BN;
        #pragma unroll
        for (int ks = 0; ks < 4; ks++) {
            const int k = ks * 8 + tig;
            uint32_t af[MT][4];
            #pragma unroll
            for (int mt = 0; mt < MT; mt++) {
                int m = wm * WM + mt * 16 + grp;
                int sw = (m & 7) << 2;
                af[mt][0] = __float_as_uint(Ab[m * BK + (k ^ sw)]);
                af[mt][1] = __float_as_uint(Ab[(m + 8) * BK + (k ^ sw)]);
                af[mt][2] = __float_as_uint(Ab[m * BK + ((k + 4) ^ sw)]);
                af[mt][3] = __float_as_uint(Ab[(m + 8) * BK + ((k + 4) ^ sw)]);
            }
            uint32_t bf[NT][2];
            #pragma unroll
            for (int nt = 0; nt < NT; nt++) {
                int n = wn * WN + nt * 8 + grp;
                int sw = (k & 3) << 3;
                bf[nt][0] = __float_as_uint(Bb[k * BN + (n ^ sw)]);
                bf[nt][1] = __float_as_uint(Bb[(k + 4) * BN + (n ^ sw)]);
            }
            #pragma unroll
            for (int mt = 0; mt < MT; mt++)
                #pragma unroll
                for (int nt = 0; nt < NT; nt++)
                    mma8(acc[mt][nt], af[mt], bf[nt]);
        }
    };

    ldgAB(0);
    sts(0);
    __syncthreads();
    const int nIter = K / BK;
    for (int t = 0; t < nIter; t++) {
        if (t + 1 < nIter) ldgAB((t + 1) * BK);
        compute(t & 1);
        if (t + 1 < nIter) {
            sts((t + 1) & 1);
            __syncthreads();
        }
    }

    #pragma unroll
    for (int mt = 0; mt < MT; mt++) {
        int m = m0 + wm * WM + mt * 16 + grp;
        #pragma unroll
        for (int nt = 0; nt < NT; nt++) {
            int n = n0 + wn * WN + nt * 8 + tig * 2;
            float bx = bias[n], by = bias[n + 1];
            float2 o1, o2;
            o1.x = alpha * acc[mt][nt][0] + bbeta * bx;
            o1.y = alpha * acc[mt][nt][1] + bbeta * by;
            o2.x = alpha * acc[mt][nt][2] + bbeta * bx;
            o2.y = alpha * acc[mt][nt][3] + bbeta * by;
            if (RELU) {
                o1.x = fmaxf(o1.x, 0.f); o1.y = fmaxf(o1.y, 0.f);
                o2.x = fmaxf(o2.x, 0.f); o2.y = fmaxf(o2.y, 0.f);
            }
            *(float2*)&C[(long)m * ldc + n] = o1;
            *(float2*)&C[(long)(m + 8) * ldc + n] = o2;
        }
    }
}

// ---------------- M[h] = K[h]^T @ V[h]  (64x64, reduce over 2048) ----------------
__global__ void __launch_bounds__(256) ktv_kernel(
    const float* __restrict__ Kmat, const float* __restrict__ V, float* __restrict__ M)
{
    int h = blockIdx.y, split = blockIdx.x;
    const float* Kh = Kmat + (long)h*NTOK*DHEAD;
    const float* Vh = V    + (long)h*NTOK*DHEAD;
    __shared__ __align__(16) float Ks[32][68];
    __shared__ __align__(16) float Vs[32][68];
    int tid = threadIdx.x, tx = tid & 15, ty = tid >> 4;
    float acc[4][4] = {};
    int nbeg = split * 256;
    for (int n0 = nbeg; n0 < nbeg + 256; n0 += 32) {
        for (int i = tid; i < 512; i += 256) {
            int r = i >> 4, c4 = (i & 15) << 2;
            *(float4*)&Ks[r][c4] = *(const float4*)&Kh[(long)(n0+r)*DHEAD + c4];
            *(float4*)&Vs[r][c4] = *(const float4*)&Vh[(long)(n0+r)*DHEAD + c4];
        }
        __syncthreads();
        #pragma unroll
        for (int n = 0; n < 32; n++) {
            float4 a = *(const float4*)&Ks[n][ty*4];
            float4 b = *(const float4*)&Vs[n][tx*4];
            float av[4] = {a.x, a.y, a.z, a.w};
            float bv[4] = {b.x, b.y, b.z, b.w};
            #pragma unroll
            for (int ik = 0; ik < 4; ik++)
                #pragma unroll
                for (int iv = 0; iv < 4; iv++)
                    acc[ik][iv] += av[ik] * bv[iv];
        }
        __syncthreads();
    }
    float* Mh = M + h*DHEAD*DHEAD;
    #pragma unroll
    for (int ik = 0; ik < 4; ik++)
        #pragma unroll
        for (int iv = 0; iv < 4; iv++)
            atomicAdd(&Mh[(ty*4+ik)*DHEAD + tx*4+iv], acc[ik][iv]);
}

// ---------------- LSE via tensor cores + fused online logsumexp ----------------
// LSE[h,m] = logsumexp_n( Q[h,n]·K[h,m] / 8 ).  Block: 64 keys, loops queries.
// mma: m-dim = keys (A = K tile), n-dim = queries (B = Q tile), k-dim = dhead.
__device__ __forceinline__ void omerge(float& m, float& s, float m2, float s2) {
    float nm = fmaxf(m, m2);
    s = s * __expf(m - nm) + s2 * __expf(m2 - nm);
    m = nm;
}

__global__ void __launch_bounds__(256, 1) lse_mma_kernel(
    const float* __restrict__ Q, const float* __restrict__ Kmat, float* __restrict__ LSE)
{
    extern __shared__ float sm[];
    float* Ks  = sm;                       // [64*64]     swizzled k^((m&7)<<2)
    float* Qs  = sm + 64 * 64;             // [2][128*64] swizzled k^((n&7)<<2)
    float* red = sm + 64 * 64 + 2 * 128 * 64;  // [2*64*2]

    int h = blockIdx.y, m0 = blockIdx.x * 64;
    const float* Qh = Q    + (long)h * NTOK * DHEAD;
    const float* Kh = Kmat + (long)h * NTOK * DHEAD;
    int tid = threadIdx.x, wid = tid >> 5, lane = tid & 31;
    int grp = lane >> 2, tig = lane & 3;
    int wm = wid & 3, wq = wid >> 2;   // 4 key-warps x 2 query-warps

    // K tile: 64x64 -> swizzled smem
    #pragma unroll
    for (int t = 0; t < 4; t++) {
        int i = tid + t * 256;
        int r = i >> 4, c = (i & 15) * 4;
        float4 v = *(const float4*)&Kh[(long)(m0 + r) * 64 + c];
        *(float4*)&Ks[r * 64 + (c ^ ((r & 7) << 2))] = cvt4(v);
    }

    float4 qr[8];
    auto ldgQ = [&](int nq) {
        #pragma unroll
        for (int t = 0; t < 8; t++) {
            int i = tid + t * 256;
            int r = i >> 4, c = (i & 15) * 4;
            qr[t] = *(const float4*)&Qh[(long)(nq + r) * 64 + c];
        }
    };
    auto stsQ = [&](int buf) {
        float* Qb = Qs + buf * 128 * 64;
        #pragma unroll
        for (int t = 0; t < 8; t++) {
            int i = tid + t * 256;
            int r = i >> 4, c = (i & 15) * 4;
            *(float4*)&Qb[r * 64 + (c ^ ((r & 7) << 2))] = cvt4(qr[t]);
        }
    };

    float rm0 = -1e30f, rs0 = 0.f, rm1 = -1e30f, rs1 = 0.f;

    ldgQ(0);
    stsQ(0);
    __syncthreads();

    for (int it = 0; it < 16; it++) {
        if (it + 1 < 16) ldgQ((it + 1) * 128);
        const float* Qb = Qs + (it & 1) * 128 * 64;

        float acc[8][4] = {};
        #pragma unroll
        for (int ks = 0; ks < 8; ks++) {
            const int k = ks * 8 + tig;
            uint32_t af[4];
            int m = wm * 16 + grp;
            int swA = (m & 7) << 2;
            af[0] = __float_as_uint(Ks[m * 64 + (k ^ swA)]);
            af[1] = __float_as_uint(Ks[(m + 8) * 64 + (k ^ swA)]);
            af[2] = __float_as_uint(Ks[m * 64 + ((k + 4) ^ swA)]);
            af[3] = __float_as_uint(Ks[(m + 8) * 64 + ((k + 4) ^ swA)]);
            #pragma unroll
            for (int nt = 0; nt < 8; nt++) {
                int n = wq * 64 + nt * 8 + grp;
                int swB = (n & 7) << 2;
                uint32_t bf[2];
                bf[0] = __float_as_uint(Qb[n * 64 + (k ^ swB)]);
                bf[1] = __float_as_uint(Qb[n * 64 + ((k + 4) ^ swB)]);
                mma8(acc[nt], af, bf);
            }
        }

        // fold 16 scores per row into running (max,sum). rows: grp, grp+8.
        float lm0 = -1e30f, lm1 = -1e30f;
        #pragma unroll
        for (int nt = 0; nt < 8; nt++) {
            lm0 = fmaxf(lm0, fmaxf(acc[nt][0], acc[nt][1]));
            lm1 = fmaxf(lm1, fmaxf(acc[nt][2], acc[nt][3]));
        }
        lm0 *= 0.125f; lm1 *= 0.125f;
        float ls0 = 0.f, ls1 = 0.f;
        #pragma unroll
        for (int nt = 0; nt < 8; nt++) {
            ls0 += __expf(acc[nt][0] * 0.125f - lm0) + __expf(acc[nt][1] * 0.125f - lm0);
            ls1 += __expf(acc[nt][2] * 0.125f - lm1) + __expf(acc[nt][3] * 0.125f - lm1);
        }
        omerge(rm0, rs0, lm0, ls0);
        omerge(rm1, rs1, lm1, ls1);

        if (it + 1 < 16) {
            stsQ((it + 1) & 1);
            __syncthreads();
        }
    }

    // reduce across the 4 lanes sharing a row (tig), then across query-warps.
    #pragma unroll
    for (int d = 1; d < 4; d <<= 1) {
        float om0 = __shfl_xor_sync(0xffffffffu, rm0, d);
        float os0 = __shfl_xor_sync(0xffffffffu, rs0, d);
        omerge(rm0, rs0, om0, os0);
        float om1 = __shfl_xor_sync(0xffffffffu, rm1, d);
        float os1 = __shfl_xor_sync(0xffffffffu, rs1, d);
        omerge(rm1, rs1, om1, os1);
    }
    __syncthreads();
    if (tig == 0) {
        int k0 = wm * 16 + grp;
        red[(wq * 64 + k0) * 2 + 0] = rm0;
        red[(wq * 64 + k0) * 2 + 1] = rs0;
        red[(wq * 64 + k0 + 8) * 2 + 0] = rm1;
        red[(wq * 64 + k0 + 8) * 2 + 1] = rs1;
    }
    __syncthreads();
    if (tid < 64) {
        float ma = red[tid * 2], sa = red[tid * 2 + 1];
        float mb = red[(64 + tid) * 2], sb = red[(64 + tid) * 2 + 1];
        omerge(ma, sa, mb, sb);
        LSE[h * NTOK + m0 + tid] = ma + logf(sa);
    }
}

// ---------------- c[h,v] = sum_m LSE[h,m] * V[h,m,v] ----------------
__global__ void __launch_bounds__(256) cvec_kernel(
    const float* __restrict__ V, const float* __restrict__ LSE, float* __restrict__ c)
{
    int h = blockIdx.x, tid = threadIdx.x;
    int v = tid & 63, part = tid >> 6;
    const float* Vh = V   + (long)h*NTOK*DHEAD;
    const float* Lh = LSE + (long)h*NTOK;
    float s = 0.0f;
    for (int m = part*512; m < part*512 + 512; m++)
        s += Lh[m] * Vh[(long)m*DHEAD + v];
    __shared__ float sh[256];
    sh[tid] = s;
    __syncthreads();
    if (part == 0)
        c[h*DHEAD + v] = sh[v] + sh[64+v] + sh[128+v] + sh[192+v];
}

// ---------------- layer norm ----------------
__device__ __forceinline__ float blockReduceSum256(float v)
{
    __shared__ float sh[8];
    int lane = threadIdx.x & 31, w = threadIdx.x >> 5;
    #pragma unroll
    for (int d = 16; d; d >>= 1) v += __shfl_xor_sync(0xffffffffu, v, d);
    __syncthreads();
    if (lane == 0) sh[w] = v;
    __syncthreads();
    float t = 0.0f;
    #pragma unroll
    for (int i = 0; i < 8; i++) t += sh[i];
    return t;
}

__global__ void __launch_bounds__(256) ln_kernel(
    const float* __restrict__ x, const float* __restrict__ r,
    const float* __restrict__ g, const float* __restrict__ b,
    float* __restrict__ out)
{
    int row = blockIdx.x, tid = threadIdx.x;
    long base = (long)row * DMOD;
    float4 xv = *(const float4*)&x[base + tid*4];
    float4 rv = *(const float4*)&r[base + tid*4];
    float v[4] = {xv.x+rv.x, xv.y+rv.y, xv.z+rv.z, xv.w+rv.w};

    float s = v[0]+v[1]+v[2]+v[3];
    s = blockReduceSum256(s);
    float mean = s * (1.0f/1024.0f);

    float d0=v[0]-mean, d1=v[1]-mean, d2=v[2]-mean, d3=v[3]-mean;
    float ss = d0*d0 + d1*d1 + d2*d2 + d3*d3;
    ss = blockReduceSum256(ss);
    float invstd = rsqrtf(ss * (1.0f/1023.0f));

    float4 gv = *(const float4*)&g[base + tid*4];
    float4 bv = *(const float4*)&b[base + tid*4];
    float4 o;
    o.x = gv.x*invstd*d0 + bv.x;
    o.y = gv.y*invstd*d1 + bv.y;
    o.z = gv.z*invstd*d2 + bv.z;
    o.w = gv.w*invstd*d3 + bv.w;
    *(float4*)&out[base + tid*4] = o;
}

// ---------------- driver ----------------
extern "C" void kernel_launch(void* const* d_in, const int* in_sizes, int n_in,
                              void* d_out, int out_size)
{
    const int*   X   = (const int*)  d_in[0];
    const float* emb = (const float*)d_in[1];
    const float* WQ  = (const float*)d_in[2];
    const float* bQ  = (const float*)d_in[3];
    const float* WK  = (const float*)d_in[4];
    const float* bK  = (const float*)d_in[5];
    const float* WV  = (const float*)d_in[6];
    const float* bV  = (const float*)d_in[7];
    const float* WO  = (const float*)d_in[8];
    const float* bO  = (const float*)d_in[9];
    const float* W1  = (const float*)d_in[10];
    const float* b1  = (const float*)d_in[11];
    const float* W2  = (const float*)d_in[12];
    const float* b2  = (const float*)d_in[13];
    const float* g1  = (const float*)d_in[14];
    const float* be1 = (const float*)d_in[15];
    const float* g2  = (const float*)d_in[16];
    const float* be2 = (const float*)d_in[17];
    float* out = (float*)d_out;

    float *h_, *h2, *Qb, *Kb, *Vb, *Zb, *Ob, *Fb, *Rb, *Mb, *LSEb, *cb;
    cudaGetSymbolAddress((void**)&h_,   g_h);
    cudaGetSymbolAddress((void**)&h2,   g_h2);
    cudaGetSymbolAddress((void**)&Qb,   g_Q);
    cudaGetSymbolAddress((void**)&Kb,   g_K);
    cudaGetSymbolAddress((void**)&Vb,   g_V);
    cudaGetSymbolAddress((void**)&Zb,   g_Z);
    cudaGetSymbolAddress((void**)&Ob,   g_O);
    cudaGetSymbolAddress((void**)&Fb,   g_F);
    cudaGetSymbolAddress((void**)&Rb,   g_R);
    cudaGetSymbolAddress((void**)&Mb,   g_M);
    cudaGetSymbolAddress((void**)&LSEb, g_LSE);
    cudaGetSymbolAddress((void**)&cb,   g_c);

    // dynamic smem budgets
    const int SMEM_G128 = 2 * (128*32 + 32*128) * 4;   // 65536
    const int SMEM_G64  = 2 * (128*32 + 32*64)  * 4;   // 49152
    const int SMEM_LSE  = (64*64 + 2*128*64 + 256) * 4; // 82944
    cudaFuncSetAttribute(mma_gemm<128,128,false>, cudaFuncAttributeMaxDynamicSharedMemorySize, SMEM_G128);
    cudaFuncSetAttribute(mma_gemm<128,128,true>,  cudaFuncAttributeMaxDynamicSharedMemorySize, SMEM_G128);
    cudaFuncSetAttribute(mma_gemm<128,64,false>,  cudaFuncAttributeMaxDynamicSharedMemorySize, SMEM_G64);
    cudaFuncSetAttribute(lse_mma_kernel,          cudaFuncAttributeMaxDynamicSharedMemorySize, SMEM_LSE);

    embed_pe_kernel<<<NTOK, 256>>>(X, emb, h_);

    for (int l = 0; l < NLAYER; l++) {
        const float* wq = WQ + (long)l*NHEAD*DMOD*DHEAD;
        const float* wk = WK + (long)l*NHEAD*DMOD*DHEAD;
        const float* wv = WV + (long)l*NHEAD*DMOD*DHEAD;
        const float* bq = bQ + (long)l*NHEAD*DHEAD;
        const float* bk = bK + (long)l*NHEAD*DHEAD;
        const float* bv = bV + (long)l*NHEAD*DHEAD;

        // Q/K/V per-head projections: [2048,1024]@[1024,64]+b, z over heads
        dim3 gqkv(1, NTOK/128, NHEAD);
        mma_gemm<128,64,false><<<gqkv, 256, SMEM_G64>>>(h_, wq, bq, Qb,
            DMOD, DMOD, DHEAD, DHEAD, 0, (long)DMOD*DHEAD, DHEAD, (long)NTOK*DHEAD, 1.f, 1.f);
        mma_gemm<128,64,false><<<gqkv, 256, SMEM_G64>>>(h_, wk, bk, Kb,
            DMOD, DMOD, DHEAD, DHEAD, 0, (long)DMOD*DHEAD, DHEAD, (long)NTOK*DHEAD, 1.f, 1.f);
        mma_gemm<128,64,false><<<gqkv, 256, SMEM_G64>>>(h_, wv, bv, Vb,
            DMOD, DMOD, DHEAD, DHEAD, 0, (long)DMOD*DHEAD, DHEAD, (long)NTOK*DHEAD, 1.f, 1.f);

        // M = K^T V per head
        cudaMemsetAsync(Mb, 0, sizeof(float)*NHEAD*DHEAD*DHEAD, 0);
        ktv_kernel<<<dim3(8, NHEAD), 256>>>(Kb, Vb, Mb);

        // column-wise logsumexp of S (over queries), tensor-core fused
        lse_mma_kernel<<<dim3(NTOK/64, NHEAD), 256, SMEM_LSE>>>(Qb, Kb, LSEb);

        // c[h] = LSE[h] · V[h]
        cvec_kernel<<<NHEAD, 256>>>(Vb, LSEb, cb);

        // attn[h] = 0.125 * Q[h] @ M[h] - c[h], written DIRECTLY into Z concat layout
        mma_gemm<128,64,false><<<gqkv, 256, SMEM_G64>>>(Qb, Mb, cb, Zb,
            DHEAD, DHEAD, DHEAD, DMOD,
            (long)NTOK*DHEAD, (long)DHEAD*DHEAD, DHEAD, (long)DHEAD, 0.125f, -1.f);

        // output projection
        mma_gemm<128,128,false><<<dim3(DMOD/128, NTOK/128, 1), 256, SMEM_G128>>>(
            Zb, WO + (long)l*DMOD*DMOD, bO + (long)l*DMOD, Ob,
            DMOD, DMOD, DMOD, DMOD, 0,0,0,0, 1.f, 1.f);

        // h2 = LN(h + O)
        ln_kernel<<<NTOK, 256>>>(h_, Ob, g1 + (long)l*NTOK*DMOD, be1 + (long)l*NTOK*DMOD, h2);

        // FFN
        mma_gemm<128,128,true><<<dim3(DFFN/128, NTOK/128, 1), 256, SMEM_G128>>>(
            h2, W1 + (long)l*DMOD*DFFN, b1 + (long)l*DFFN, Fb,
            DMOD, DMOD, DFFN, DFFN, 0,0,0,0, 1.f, 1.f);
        mma_gemm<128,128,false><<<dim3(DMOD/128, NTOK/128, 1), 256, SMEM_G128>>>(
            Fb, W2 + (long)l*DFFN*DMOD, b2 + (long)l*DMOD, Rb,
            DFFN, DFFN, DMOD, DMOD, 0,0,0,0, 1.f, 1.f);

        // h = LN(h2 + R)  (last layer writes d_out directly)
        float* dst = (l == NLAYER-1) ? out : h_;
        ln_kernel<<<NTOK, 256>>>(h2, Rb, g2 + (long)l*NTOK*DMOD, be2 + (long)l*NTOK*DMOD, dst);
    }
}